// round 12
// baseline (speedup 1.0000x reference)
#include <cuda_runtime.h>
#include <math.h>

#define NBINS 1001
#define KQ 127
#define HALFB 500
#define EPS_S 1e-4
#define IMIN 63
#define NCAND 438
#define HIST_SUB 4
#define EXP_CUT -700.0
#define BAND 2e-3f
#define GRID 592   // 4 blocks/SM x 148 SMs; __launch_bounds__(256,4) guarantees residency

__device__ unsigned int g_absmax_bits;   // zero at load; final block re-zeroes
__device__ unsigned int g_hist[NBINS];   // zero at load; final block re-zeroes
__device__ unsigned int g_csum[NBINS + 1];
__device__ unsigned int g_total;
__device__ unsigned int g_bar1, g_bar2;  // grid barrier counters (reset at end)
__device__ unsigned int g_done;          // hist scan ticket (reset at end)
__device__ unsigned int g_done2;         // kl argmin ticket (reset at end)
__device__ double g_kl[NCAND];

// ---------------- binning ----------------
// Fast path: fp32 estimate floor((c+a)*inv); provably correct unless the
// fractional part is within BAND of a boundary (estimate+edge error < 3.5e-4
// bins), in which case verify against exact fp32 linspace edges.
__device__ __forceinline__ int bin_of(float c, float a, float inv, float step) {
    float y = __fmul_rn(__fadd_rn(c, a), inv);
    int b = (int)y;
    float fr = y - (float)b;
    if (fr < BAND || fr > 1.0f - BAND) {
        float e0 = __fadd_rn(__fmul_rn((float)b, step), -a);
        float e1 = __fadd_rn(__fmul_rn((float)(b + 1), step), -a);
        b += (c >= e1) ? 1 : 0;
        b -= (c < e0) ? 1 : 0;
    }
    return max(0, min(NBINS - 1, b));
}

// ---------------- reductions ----------------
template <typename T>
__device__ __forceinline__ T warpSumT(T v) {
    #pragma unroll
    for (int o = 16; o; o >>= 1) v += __shfl_xor_sync(0xffffffffu, v, o);
    return v;
}
__device__ __forceinline__ unsigned int warpMaxU(unsigned int v) {
    #pragma unroll
    for (int o = 16; o; o >>= 1) v = max(v, __shfl_xor_sync(0xffffffffu, v, o));
    return v;
}
__device__ __forceinline__ double warpMaxD(double v) {
    #pragma unroll
    for (int o = 16; o; o >>= 1) v = fmax(v, __shfl_xor_sync(0xffffffffu, v, o));
    return v;
}

struct RedShared {
    double d[16];
    unsigned long long u[8];
};

__device__ __forceinline__ double blockSumD(double v, RedShared* sh) {
    int lane = threadIdx.x & 31, w = threadIdx.x >> 5;
    v = warpSumT(v);
    if (lane == 0) sh->d[w] = v;
    __syncthreads();
    if (w == 0) {
        double t = (lane < 8) ? sh->d[lane] : 0.0;
        t = warpSumT(t);
        if (lane == 0) sh->d[0] = t;
    }
    __syncthreads();
    double r = sh->d[0];
    __syncthreads();
    return r;
}
__device__ __forceinline__ void blockSum2(double& a, double& b, RedShared* sh) {
    int lane = threadIdx.x & 31, w = threadIdx.x >> 5;
    a = warpSumT(a); b = warpSumT(b);
    if (lane == 0) { sh->d[w] = a; sh->d[8 + w] = b; }
    __syncthreads();
    if (w == 0) {
        double ta = (lane < 8) ? sh->d[lane] : 0.0;
        double tb = (lane < 8) ? sh->d[8 + lane] : 0.0;
        ta = warpSumT(ta); tb = warpSumT(tb);
        if (lane == 0) { sh->d[0] = ta; sh->d[8] = tb; }
    }
    __syncthreads();
    a = sh->d[0]; b = sh->d[8];
    __syncthreads();
}
__device__ __forceinline__ void blockSumU_MaxD(unsigned int& s, double& mx, RedShared* sh) {
    int lane = threadIdx.x & 31, w = threadIdx.x >> 5;
    s = warpSumT(s); mx = warpMaxD(mx);
    if (lane == 0) { sh->u[w] = s; sh->d[w] = mx; }
    __syncthreads();
    if (w == 0) {
        unsigned int ts = (lane < 8) ? (unsigned int)sh->u[lane] : 0u;
        double tm = (lane < 8) ? sh->d[lane] : -1e300;
        ts = warpSumT(ts); tm = warpMaxD(tm);
        if (lane == 0) { sh->u[0] = ts; sh->d[0] = tm; }
    }
    __syncthreads();
    s = (unsigned int)sh->u[0]; mx = sh->d[0];
    __syncthreads();
}
__device__ __forceinline__ unsigned int blockMaxU(unsigned int v, RedShared* sh) {
    int lane = threadIdx.x & 31, w = threadIdx.x >> 5;
    v = warpMaxU(v);
    if (lane == 0) sh->u[w] = v;
    __syncthreads();
    if (w == 0) {
        unsigned int t = (lane < 8) ? (unsigned int)sh->u[lane] : 0u;
        t = warpMaxU(t);
        if (lane == 0) sh->u[0] = t;
    }
    __syncthreads();
    unsigned int r = (unsigned int)sh->u[0];
    __syncthreads();
    return r;
}

// grid-wide spin barrier (all GRID blocks resident by __launch_bounds__)
__device__ __forceinline__ void grid_sync(unsigned int* ctr, int G) {
    __threadfence();
    __syncthreads();
    if (threadIdx.x == 0) {
        atomicAdd(ctr, 1u);
        while (*(volatile unsigned int*)ctr < (unsigned int)G) { }
    }
    __syncthreads();
}

// ---------------- one persistent kernel: absmax | hist+scan | kl | argmin ----------------
__global__ void __launch_bounds__(256, 4) fused_kernel(const float* __restrict__ x, int n,
                                                       float* __restrict__ out) {
    __shared__ unsigned int sh[HIST_SUB][NBINS];
    __shared__ double s_q[KQ];          // properly aligned (was the R11 trap)
    __shared__ unsigned int s_nm[KQ];
    __shared__ RedShared s_red;

    const int n4 = n >> 2;
    const float4* x4 = (const float4*)x;
    const int G = gridDim.x;
    const int b = blockIdx.x;
    const int lo = (int)((long long)b * n4 / G);
    const int hi = (int)((long long)(b + 1) * n4 / G);
    const int lane = threadIdx.x & 31, w = threadIdx.x >> 5;

    {
        unsigned int* shf = &sh[0][0];
        for (int k = threadIdx.x; k < HIST_SUB * NBINS; k += 256) shf[k] = 0u;
    }

    // ---- phase 1: absmax over own chunk (forward sweep) ----
    float m = 0.f;
    for (int idx = lo + threadIdx.x; idx < hi; idx += 256) {
        float4 v = x4[idx];
        m = fmaxf(m, fmaxf(fmaxf(fabsf(v.x), fabsf(v.y)), fmaxf(fabsf(v.z), fabsf(v.w))));
    }
    if (b == 0 && threadIdx.x < (n & 3))
        m = fmaxf(m, fabsf(x[n4 * 4 + threadIdx.x]));
    #pragma unroll
    for (int o = 16; o; o >>= 1) m = fmaxf(m, __shfl_xor_sync(0xffffffffu, m, o));
    if (lane == 0) s_red.d[w] = (double)m;
    __syncthreads();
    if (w == 0) {
        double t = (lane < 8) ? s_red.d[lane] : 0.0;
        t = warpMaxD(t);
        if (lane == 0) atomicMax(&g_absmax_bits, __float_as_uint((float)t));
    }

    grid_sync(&g_bar1, G);

    const float a = __uint_as_float(*(volatile unsigned int*)&g_absmax_bits);
    const float step = __fdiv_rn(__fmul_rn(2.0f, a), (float)NBINS);
    const float inv = __fdiv_rn((float)NBINS, __fmul_rn(2.0f, a));
    // lane-indexed sub-histogram: conflicting lanes spread over 4 bank-distinct copies
    unsigned int* hsub = sh[threadIdx.x & (HIST_SUB - 1)];

    // ---- phase 2: histogram over own chunk, REVERSE sweep (LIFO L2 reuse) ----
    for (int idx = hi - 1 - threadIdx.x; idx >= lo; idx -= 256) {
        float4 v = x4[idx];
        atomicAdd(&hsub[bin_of(v.x, a, inv, step)], 1u);
        atomicAdd(&hsub[bin_of(v.y, a, inv, step)], 1u);
        atomicAdd(&hsub[bin_of(v.z, a, inv, step)], 1u);
        atomicAdd(&hsub[bin_of(v.w, a, inv, step)], 1u);
    }
    if (b == 0 && threadIdx.x < (n & 3)) {
        float c = x[n4 * 4 + threadIdx.x];
        atomicAdd(&hsub[bin_of(c, a, inv, step)], 1u);
    }
    __syncthreads();
    for (int k = threadIdx.x; k < NBINS; k += 256) {
        unsigned int s = 0;
        #pragma unroll
        for (int j = 0; j < HIST_SUB; j++) s += sh[j][k];
        if (s) atomicAdd(&g_hist[k], s);
    }

    // ---- last hist block builds the exclusive prefix scan ----
    __shared__ unsigned int s_last;
    __threadfence();
    if (threadIdx.x == 0)
        s_last = (atomicAdd(&g_done, 1u) == (unsigned int)(G - 1)) ? 1u : 0u;
    __syncthreads();
    if (s_last) {
        __threadfence();
        __shared__ unsigned int tsum[256];
        __shared__ unsigned int wex[9];
        int t = threadIdx.x;
        unsigned int hv[4], loc[4];
        unsigned int s = 0;
        #pragma unroll
        for (int j = 0; j < 4; j++) {
            int k = 4 * t + j;
            hv[j] = (k < NBINS) ? *(volatile unsigned int*)&g_hist[k] : 0u;
            loc[j] = s;
            s += hv[j];
        }
        tsum[t] = s;
        __syncthreads();
        unsigned int v = tsum[t];
        unsigned int inc = v;
        #pragma unroll
        for (int o = 1; o < 32; o <<= 1) {
            unsigned int q = __shfl_up_sync(0xffffffffu, inc, o);
            if (lane >= o) inc += q;
        }
        if (lane == 31) wex[w + 1] = inc;
        __syncthreads();
        if (t == 0) {
            wex[0] = 0u;
            for (int j = 1; j < 8; j++) wex[j + 1] += wex[j];
        }
        __syncthreads();
        unsigned int base = wex[w] + inc - v;
        #pragma unroll
        for (int j = 0; j < 4; j++) {
            int k = 4 * t + j;
            if (k < NBINS) g_csum[k] = base + loc[j];
        }
        if (t == 255) {
            unsigned int tot = base + loc[3] + hv[3];
            g_csum[NBINS] = tot;
            g_total = tot;
        }
    }

    grid_sync(&g_bar2, G);

    // ---- phase 3: per-candidate KL on blocks 0..NCAND-1 ----
    if (b < NCAND) {
        const int i = IMIN + b;
        const int L = 2 * i + 1;
        const int start = HALFB - i;
        const int stop = HALFB + i + 1;
        const int mseg = L / KQ;

        unsigned int* s_h = sh[0];   // reuse hist smem row 0 (uint, alignment fine)

        for (int k = threadIdx.x; k < NBINS; k += 256) s_h[k] = g_hist[k];
        __syncthreads();

        const unsigned int left = g_csum[start];
        const unsigned int right = g_total - g_csum[stop];

        unsigned int pv[4], vv[4];
        unsigned int mpi = 0u;
        #pragma unroll
        for (int t = 0; t < 4; t++) {
            int k = threadIdx.x + t * 256;
            pv[t] = 0u; vv[t] = 0u;
            if (k < L) {
                unsigned int v = s_h[k + start];
                vv[t] = v;
                unsigned int p = v;
                if (k == 0) p += left;
                if (k == L - 1) p += right;
                pv[t] = p;
                mpi = max(mpi, p);
            }
        }
        mpi = blockMaxU(mpi, &s_red);
        const double mp = mpi ? (double)mpi : EPS_S;

        double qseg = 0.0;
        unsigned int nmj = 0u;
        if (threadIdx.x < KQ) {
            int j = threadIdx.x;
            int k0 = j * mseg;
            int k1 = (j == KQ - 1) ? L : (k0 + mseg);
            unsigned int sum = 0u, cnt = 0u;
            for (int k = k0; k < k1; k++) {
                unsigned int v = s_h[start + k];
                sum += v;
                cnt += (v != 0u && k != L - 1) ? 1u : 0u;
            }
            nmj = cnt;
            if (cnt > 0u) qseg = (double)sum / (double)cnt;
            s_q[j] = qseg;
            s_nm[j] = cnt;
        }
        unsigned int nnzq = nmj;
        double mq = (threadIdx.x < KQ && nmj > 0u) ? qseg : -1e300;
        blockSumU_MaxD(nnzq, mq, &s_red);
        mq = fmax(mq, EPS_S);

        double sq = 0.0;
        if (threadIdx.x < KQ && nmj > 0u) {
            double dq = qseg - mq;
            if (dq > EXP_CUT) sq = (double)nmj * exp(dq);
        }
        if (threadIdx.x == 0) {
            double dz = EPS_S - mq;
            if (dz > EXP_CUT) sq += (double)(L - (int)nnzq) * exp(dz);
        }
        // sp: integer gate (inclusion of borderline bins is harmless: terms < e^-700)
        double sp = 0.0;
        {
            unsigned int gate_u = (mpi > 700u) ? (mpi - 700u) : 0u;
            #pragma unroll
            for (int t = 0; t < 4; t++) {
                int k = threadIdx.x + t * 256;
                if (k < L && pv[t] >= gate_u) {
                    double pl = pv[t] ? (double)pv[t] : EPS_S;
                    sp += exp(pl - mp);
                }
            }
        }
        blockSum2(sp, sq, &s_red);
        const double lZp = mp + log(sp);
        const double lZq = mq + log(sq);

        double kl = 0.0;
        {
            double g2 = lZp + EXP_CUT;
            unsigned int gate2 = (g2 <= 0.0) ? 0u : (unsigned int)g2;  // floor; inclusive
            #pragma unroll
            for (int t = 0; t < 4; t++) {
                int k = threadIdx.x + t * 256;
                if (k < L && pv[t] >= gate2) {
                    double pl = pv[t] ? (double)pv[t] : EPS_S;
                    int seg = min(k / mseg, KQ - 1);
                    bool assigned = (vv[t] != 0u) && (k != L - 1) && (s_nm[seg] > 0u);
                    double ql = assigned ? s_q[seg] : EPS_S;
                    double lp = pl - lZp;
                    double lq = ql - lZq;
                    kl += exp(lp) * (lp - lq);
                }
            }
        }
        kl = blockSumD(kl, &s_red);
        if (threadIdx.x == 0)
            g_kl[b] = (nnzq > 0u) ? kl : (double)INFINITY;

        // ---- last kl block: argmin + output + global-state reset ----
        __shared__ unsigned int s_fin;
        __threadfence();
        if (threadIdx.x == 0)
            s_fin = (atomicAdd(&g_done2, 1u) == (unsigned int)(NCAND - 1)) ? 1u : 0u;
        __syncthreads();
        if (s_fin) {
            __threadfence();
            __shared__ double sv[256];
            __shared__ int si[256];
            double best = (double)INFINITY;
            int bi = 0x7fffffff;
            for (int k = threadIdx.x; k < NCAND; k += 256) {
                double v = *(volatile double*)&g_kl[k];
                if (v < best || (v == best && k < bi)) { best = v; bi = k; }
            }
            sv[threadIdx.x] = best; si[threadIdx.x] = bi;
            __syncthreads();
            for (int s = 128; s > 0; s >>= 1) {
                if (threadIdx.x < s) {
                    double vo = sv[threadIdx.x + s];
                    int io = si[threadIdx.x + s];
                    if (vo < sv[threadIdx.x] || (vo == sv[threadIdx.x] && io < si[threadIdx.x])) {
                        sv[threadIdx.x] = vo; si[threadIdx.x] = io;
                    }
                }
                __syncthreads();
            }
            if (threadIdx.x == 0) {
                int ib = IMIN + si[0];
                float aa = __uint_as_float(g_absmax_bits);
                double thr = -(double)aa + 2.0 * (double)aa * (double)(ib + HALFB + 1) / (double)NBINS;
                out[0] = (float)thr;
                // reset all global state for the next call/replay
                g_absmax_bits = 0u;
                g_bar1 = 0u;
                g_bar2 = 0u;
                g_done = 0u;
                g_done2 = 0u;
            }
            for (int k = threadIdx.x; k < NBINS; k += 256) g_hist[k] = 0u;
        }
    }
}

extern "C" void kernel_launch(void* const* d_in, const int* in_sizes, int n_in,
                              void* d_out, int out_size) {
    const float* x = (const float*)d_in[0];
    int n = in_sizes[0];
    fused_kernel<<<GRID, 256>>>(x, n, (float*)d_out);
}